// round 13
// baseline (speedup 1.0000x reference)
#include <cuda_runtime.h>
#include <cuda_bf16.h>
#include <math.h>

#define DD 1024
#define FF 4096
#define LL 24
#define VV 50277
#define NB 148
#define NT 1024
#define NWARPS_TOTAL (NB * 32)

// ---- persistent device scratch (no allocations allowed) ----
__device__ float g_x[DD];
__device__ float g_kk[DD];
__device__ float g_vv[DD];
__device__ float g_r[DD];
__device__ float g_k2[FF];
__device__ float g_r2[DD];
__device__ unsigned g_count = 0;
__device__ unsigned g_sense = 0;

// ---- grid-wide sense-reversing barrier ----
__device__ __forceinline__ void grid_sync(unsigned& sense) {
    __syncthreads();
    if (threadIdx.x == 0) {
        __threadfence();              // release (gpu scope)
        sense ^= 1u;
        unsigned old = atomicAdd(&g_count, 1u);
        if (old == (unsigned)(gridDim.x - 1)) {
            g_count = 0u;
            __threadfence();
            atomicExch(&g_sense, sense);
        } else {
            while (*((volatile unsigned*)&g_sense) != sense) { __nanosleep(64); }
        }
        __threadfence();              // acquire
    }
    __syncthreads();
}

// ---- block-wide sum over 1024 threads ----
__device__ __forceinline__ float blk_sum(float v, float* red) {
#pragma unroll
    for (int o = 16; o > 0; o >>= 1) v += __shfl_xor_sync(0xffffffffu, v, o);
    if ((threadIdx.x & 31) == 0) red[threadIdx.x >> 5] = v;
    __syncthreads();
    if (threadIdx.x < 32) {
        float s = red[threadIdx.x];
#pragma unroll
        for (int o = 16; o > 0; o >>= 1) s += __shfl_xor_sync(0xffffffffu, s, o);
        if (threadIdx.x == 0) red[0] = s;
    }
    __syncthreads();
    float r = red[0];
    __syncthreads();
    return r;
}

// layernorm for element tid (one element per thread, D=1024 = blockDim)
__device__ __forceinline__ float block_ln(float v, float w, float b, float* red) {
    float mean = blk_sum(v, red) * (1.0f / 1024.0f);
    float d = v - mean;
    float var = blk_sum(d * d, red) * (1.0f / 1024.0f);
    return d * rsqrtf(var + 1e-5f) * w + b;
}

// warp dot of length-1024 row (float4 lanes, streaming loads) + full warp reduce
__device__ __forceinline__ float dot1024(const float* __restrict__ W,
                                         const float* __restrict__ v, int lane) {
    const float4* w4 = (const float4*)W;
    const float4* v4 = (const float4*)v;
    float acc = 0.f;
#pragma unroll
    for (int i = lane; i < 256; i += 32) {
        float4 a = __ldcs(&w4[i]);   // weights: used once, evict-first
        float4 b = v4[i];
        acc += a.x * b.x + a.y * b.y + a.z * b.z + a.w * b.w;
    }
#pragma unroll
    for (int o = 16; o > 0; o >>= 1) acc += __shfl_xor_sync(0xffffffffu, acc, o);
    return acc;
}

__global__ void __launch_bounds__(NT, 1) rwkv_kernel(
    const float* __restrict__ token_embd, const float* __restrict__ state,
    const float* __restrict__ emb_ln_w, const float* __restrict__ emb_ln_b,
    const float* __restrict__ ln1_w, const float* __restrict__ ln1_b,
    const float* __restrict__ ln2_w, const float* __restrict__ ln2_b,
    const float* __restrict__ att_tmk, const float* __restrict__ att_tmv,
    const float* __restrict__ att_tmr, const float* __restrict__ att_tf,
    const float* __restrict__ att_td, const float* __restrict__ att_kw,
    const float* __restrict__ att_vw, const float* __restrict__ att_rw,
    const float* __restrict__ att_ow, const float* __restrict__ ffn_tmk,
    const float* __restrict__ ffn_tmr, const float* __restrict__ ffn_kw,
    const float* __restrict__ ffn_vw, const float* __restrict__ ffn_rw,
    const float* __restrict__ out_ln_w, const float* __restrict__ out_ln_b,
    const float* __restrict__ head_w,
    float* __restrict__ out_logits, float* __restrict__ out_state) {

    __shared__ float sh_a[DD];
    __shared__ float sh_b[DD];
    __shared__ float sh_c[DD];
    __shared__ float sh_k2[FF];
    __shared__ float red[64];

    const int tid = threadIdx.x;
    const int lane = tid & 31;
    const int wid = tid >> 5;
    const int gwarp = blockIdx.x * 32 + wid;
    unsigned sense = 0;

    // ===== encoder: x0 = LN(token_embd) =====
    {
        float v = token_embd[tid];
        float xn = block_ln(v, emb_ln_w[tid], emb_ln_b[tid], red);
        if (blockIdx.x == 0) g_x[tid] = xn;
    }
    grid_sync(sense);  // barrier 1

    for (int l = 0; l < LL; ++l) {
        const size_t lD = (size_t)l * DD;
        const size_t lDD = (size_t)l * DD * DD;

        // ===== phase A: LN1 + time-mix interpolation + {kw,vw,rw} matvecs =====
        {
            float xcur = g_x[tid];
            float xn = block_ln(xcur, ln1_w[lD + tid], ln1_b[lD + tid], red);
            float s_att = state[(size_t)(l * 5 + 1) * DD + tid];
            float tmk = att_tmk[lD + tid], tmv = att_tmv[lD + tid], tmr = att_tmr[lD + tid];
            sh_a[tid] = xn * tmk + s_att * (1.f - tmk);
            sh_b[tid] = xn * tmv + s_att * (1.f - tmv);
            sh_c[tid] = xn * tmr + s_att * (1.f - tmr);
            if (blockIdx.x == 0) out_state[(size_t)(l * 5 + 1) * DD + tid] = xn;
            __syncthreads();

            for (int row = gwarp; row < 3 * DD; row += NWARPS_TOTAL) {
                int m = row >> 10;
                int rr = row & (DD - 1);
                const float* W;
                const float* vin;
                if (m == 0)      { W = att_kw + lDD + (size_t)rr * DD; vin = sh_a; }
                else if (m == 1) { W = att_vw + lDD + (size_t)rr * DD; vin = sh_b; }
                else             { W = att_rw + lDD + (size_t)rr * DD; vin = sh_c; }
                float acc = dot1024(W, vin, lane);
                if (lane == 0) {
                    if (m == 0)      g_kk[rr] = acc;
                    else if (m == 1) g_vv[rr] = acc;
                    else             g_r[rr] = 1.f / (1.f + __expf(-acc));
                }
            }
        }
        grid_sync(sense);

        // ===== phase B: WKV elementwise (redundant per block) + ow matvec into x =====
        {
            float kk = g_kk[tid], vv = g_vv[tid], r = g_r[tid];
            float aa = state[(size_t)(l * 5 + 2) * DD + tid];
            float bb = state[(size_t)(l * 5 + 3) * DD + tid];
            float pp = state[(size_t)(l * 5 + 4) * DD + tid];
            float tf = att_tf[lD + tid];
            float td = att_td[lD + tid];
            float ww = tf + kk;
            float p = fmaxf(pp, ww);
            float e1 = expf(pp - p);
            float e2 = expf(ww - p);
            float a = e1 * aa + e2 * vv;
            float b = e1 * bb + e2;
            sh_a[tid] = r * (a / b);  // rab
            float ww2 = pp + td;
            float p2 = fmaxf(ww2, kk);
            float f1 = expf(ww2 - p2);
            float f2 = expf(kk - p2);
            if (blockIdx.x == 0) {
                out_state[(size_t)(l * 5 + 2) * DD + tid] = f1 * aa + f2 * vv;
                out_state[(size_t)(l * 5 + 3) * DD + tid] = f1 * bb + f2;
                out_state[(size_t)(l * 5 + 4) * DD + tid] = p2;
            }
            __syncthreads();

            // ow @ rab : 1024 rows, 4 warps per row (chunks of 256 cols), 8 rows/block/iter
            for (int g = blockIdx.x; g < 128; g += NB) {
                int rloc = wid >> 2;
                int chunk = wid & 3;
                int row = g * 8 + rloc;
                const float4* w4 = (const float4*)(att_ow + lDD + (size_t)row * DD) + chunk * 64;
                const float4* v4 = (const float4*)sh_a + chunk * 64;
                float acc = 0.f;
#pragma unroll
                for (int i = lane; i < 64; i += 32) {
                    float4 aw = __ldcs(&w4[i]);
                    float4 bv = v4[i];
                    acc += aw.x * bv.x + aw.y * bv.y + aw.z * bv.z + aw.w * bv.w;
                }
#pragma unroll
                for (int o = 16; o > 0; o >>= 1) acc += __shfl_xor_sync(0xffffffffu, acc, o);
                if (lane == 0) red[wid] = acc;
                __syncthreads();
                if (tid < 8) {
                    int row2 = g * 8 + tid;
                    float sum = red[tid * 4] + red[tid * 4 + 1] + red[tid * 4 + 2] + red[tid * 4 + 3];
                    g_x[row2] += sum;
                }
                __syncthreads();
            }
        }
        grid_sync(sense);

        // ===== phase C: LN2 + channel-mix interpolation + {fkw,frw} matvecs =====
        {
            float xcur = g_x[tid];
            float xn2 = block_ln(xcur, ln2_w[lD + tid], ln2_b[lD + tid], red);
            float s_ffn = state[(size_t)(l * 5 + 0) * DD + tid];
            float tmk = ffn_tmk[lD + tid], tmr = ffn_tmr[lD + tid];
            sh_a[tid] = xn2 * tmk + s_ffn * (1.f - tmk);
            sh_b[tid] = xn2 * tmr + s_ffn * (1.f - tmr);
            if (blockIdx.x == 0) out_state[(size_t)(l * 5 + 0) * DD + tid] = xn2;
            __syncthreads();

            for (int row = gwarp; row < FF + DD; row += NWARPS_TOTAL) {
                if (row < FF) {
                    const float* W = ffn_kw + (size_t)l * FF * DD + (size_t)row * DD;
                    float acc = dot1024(W, sh_a, lane);
                    if (lane == 0) {
                        float t = fmaxf(acc, 0.f);
                        g_k2[row] = t * t;
                    }
                } else {
                    int rr = row - FF;
                    const float* W = ffn_rw + lDD + (size_t)rr * DD;
                    float acc = dot1024(W, sh_b, lane);
                    if (lane == 0) g_r2[rr] = 1.f / (1.f + __expf(-acc));
                }
            }
        }
        grid_sync(sense);

        // ===== phase D: x += r2 * (fvw @ k2), rescale =====
        {
            for (int i = tid; i < FF; i += NT) sh_k2[i] = g_k2[i];
            __syncthreads();
            float scale = ((l + 1) % 6 == 0) ? 0.5f : 1.0f;
            for (int g = blockIdx.x; g < 128; g += NB) {
                int rloc = wid >> 2;
                int chunk = wid & 3;
                int row = g * 8 + rloc;
                const float4* w4 =
                    (const float4*)(ffn_vw + (size_t)l * DD * FF + (size_t)row * FF) + chunk * 256;
                const float4* v4 = (const float4*)sh_k2 + chunk * 256;
                float acc = 0.f;
#pragma unroll
                for (int i = lane; i < 256; i += 32) {
                    float4 aw = __ldcs(&w4[i]);
                    float4 bv = v4[i];
                    acc += aw.x * bv.x + aw.y * bv.y + aw.z * bv.z + aw.w * bv.w;
                }
#pragma unroll
                for (int o = 16; o > 0; o >>= 1) acc += __shfl_xor_sync(0xffffffffu, acc, o);
                if (lane == 0) red[wid] = acc;
                __syncthreads();
                if (tid < 8) {
                    int row2 = g * 8 + tid;
                    float sum = red[tid * 4] + red[tid * 4 + 1] + red[tid * 4 + 2] + red[tid * 4 + 3];
                    g_x[row2] = (g_x[row2] + g_r2[row2] * sum) * scale;
                }
                __syncthreads();
            }
        }
        grid_sync(sense);
    }

    // parity barrier (total grid_syncs must be even so g_sense returns to 0 per launch)
    grid_sync(sense);  // barrier 98

    // ===== head: logits = head_w @ LN(x) =====
    {
        float v = g_x[tid];
        float xf = block_ln(v, out_ln_w[tid], out_ln_b[tid], red);
        sh_a[tid] = xf;
        __syncthreads();
        for (int row = gwarp; row < VV; row += NWARPS_TOTAL) {
            float acc = dot1024(head_w + (size_t)row * DD, sh_a, lane);
            if (lane == 0) out_logits[row] = acc;
        }
    }
}

extern "C" void kernel_launch(void* const* d_in, const int* in_sizes, int n_in,
                              void* d_out, int out_size) {
    const float* token_embd = (const float*)d_in[0];
    const float* state      = (const float*)d_in[1];
    const float* emb_ln_w   = (const float*)d_in[2];
    const float* emb_ln_b   = (const float*)d_in[3];
    const float* ln1_w      = (const float*)d_in[4];
    const float* ln1_b      = (const float*)d_in[5];
    const float* ln2_w      = (const float*)d_in[6];
    const float* ln2_b      = (const float*)d_in[7];
    const float* att_tmk    = (const float*)d_in[8];
    const float* att_tmv    = (const float*)d_in[9];
    const float* att_tmr    = (const float*)d_in[10];
    const float* att_tf     = (const float*)d_in[11];
    const float* att_td     = (const float*)d_in[12];
    const float* att_kw     = (const float*)d_in[13];
    const float* att_vw     = (const float*)d_in[14];
    const float* att_rw     = (const float*)d_in[15];
    const float* att_ow     = (const float*)d_in[16];
    const float* ffn_tmk    = (const float*)d_in[17];
    const float* ffn_tmr    = (const float*)d_in[18];
    const float* ffn_kw     = (const float*)d_in[19];
    const float* ffn_vw     = (const float*)d_in[20];
    const float* ffn_rw     = (const float*)d_in[21];
    const float* out_ln_w   = (const float*)d_in[22];
    const float* out_ln_b   = (const float*)d_in[23];
    const float* head_w     = (const float*)d_in[24];

    float* out_logits = (float*)d_out;                 // V = 50277
    float* out_state  = (float*)d_out + VV;            // L*5*D = 122880

    rwkv_kernel<<<NB, NT>>>(token_embd, state, emb_ln_w, emb_ln_b, ln1_w, ln1_b,
                            ln2_w, ln2_b, att_tmk, att_tmv, att_tmr, att_tf,
                            att_td, att_kw, att_vw, att_rw, att_ow, ffn_tmk,
                            ffn_tmr, ffn_kw, ffn_vw, ffn_rw, out_ln_w, out_ln_b,
                            head_w, out_logits, out_state);
}

// round 14
// speedup vs baseline: 1.0830x; 1.0830x over previous
#include <cuda_runtime.h>
#include <cuda_bf16.h>
#include <math.h>

#define DD 1024
#define FF 4096
#define LL 24
#define VV 50277
#define NB 148
#define NT 1024
#define NWARPS_TOTAL (NB * 32)          // 4736
#define NTHREADS_TOTAL (NWARPS_TOTAL * 32)  // 151552

// ---- persistent device scratch (no allocations allowed) ----
__device__ float g_x[DD];
__device__ float g_kk[DD];
__device__ float g_vv[DD];
__device__ float g_r[DD];
__device__ float g_k2[FF];
__device__ float g_r2[DD];
__device__ unsigned g_count = 0;
__device__ unsigned g_sense = 0;

__device__ __forceinline__ void l2_prefetch(const void* p) {
    asm volatile("prefetch.global.L2 [%0];" :: "l"(p));
}

// ---- grid-wide sense-reversing barrier ----
__device__ __forceinline__ void grid_sync(unsigned& sense) {
    __syncthreads();
    if (threadIdx.x == 0) {
        __threadfence();              // release (gpu scope)
        sense ^= 1u;
        unsigned old = atomicAdd(&g_count, 1u);
        if (old == (unsigned)(gridDim.x - 1)) {
            g_count = 0u;
            __threadfence();
            atomicExch(&g_sense, sense);
        } else {
            while (*((volatile unsigned*)&g_sense) != sense) { __nanosleep(64); }
        }
        __threadfence();              // acquire
    }
    __syncthreads();
}

// ---- block-wide sum over 1024 threads ----
__device__ __forceinline__ float blk_sum(float v, float* red) {
#pragma unroll
    for (int o = 16; o > 0; o >>= 1) v += __shfl_xor_sync(0xffffffffu, v, o);
    if ((threadIdx.x & 31) == 0) red[threadIdx.x >> 5] = v;
    __syncthreads();
    if (threadIdx.x < 32) {
        float s = red[threadIdx.x];
#pragma unroll
        for (int o = 16; o > 0; o >>= 1) s += __shfl_xor_sync(0xffffffffu, s, o);
        if (threadIdx.x == 0) red[0] = s;
    }
    __syncthreads();
    float r = red[0];
    __syncthreads();
    return r;
}

__device__ __forceinline__ float block_ln(float v, float w, float b, float* red) {
    float mean = blk_sum(v, red) * (1.0f / 1024.0f);
    float d = v - mean;
    float var = blk_sum(d * d, red) * (1.0f / 1024.0f);
    return d * rsqrtf(var + 1e-5f) * w + b;
}

// warp dot of one length-1024 row
__device__ __forceinline__ float dot1024(const float* __restrict__ W,
                                         const float* __restrict__ v, int lane) {
    const float4* w4 = (const float4*)W;
    const float4* v4 = (const float4*)v;
    float acc = 0.f;
#pragma unroll
    for (int i = lane; i < 256; i += 32) {
        float4 a = __ldcs(&w4[i]);
        float4 b = v4[i];
        acc += a.x * b.x + a.y * b.y + a.z * b.z + a.w * b.w;
    }
#pragma unroll
    for (int o = 16; o > 0; o >>= 1) acc += __shfl_xor_sync(0xffffffffu, acc, o);
    return acc;
}

// warp dot of TWO length-1024 rows batched (16 loads in flight, one latency batch)
__device__ __forceinline__ void dot1024x2(const float* __restrict__ W0,
                                          const float* __restrict__ W1,
                                          const float* __restrict__ v, int lane,
                                          float& o0, float& o1) {
    const float4* w0 = (const float4*)W0;
    const float4* w1 = (const float4*)W1;
    const float4* v4 = (const float4*)v;
    float a0 = 0.f, a1 = 0.f;
#pragma unroll
    for (int i = lane; i < 256; i += 32) {
        float4 b = v4[i];
        float4 x = __ldcs(&w0[i]);
        float4 y = __ldcs(&w1[i]);
        a0 += x.x * b.x + x.y * b.y + x.z * b.z + x.w * b.w;
        a1 += y.x * b.x + y.y * b.y + y.z * b.z + y.w * b.w;
    }
#pragma unroll
    for (int o = 16; o > 0; o >>= 1) {
        a0 += __shfl_xor_sync(0xffffffffu, a0, o);
        a1 += __shfl_xor_sync(0xffffffffu, a1, o);
    }
    o0 = a0; o1 = a1;
}

__global__ void __launch_bounds__(NT, 1) rwkv_kernel(
    const float* __restrict__ token_embd, const float* __restrict__ state,
    const float* __restrict__ emb_ln_w, const float* __restrict__ emb_ln_b,
    const float* __restrict__ ln1_w, const float* __restrict__ ln1_b,
    const float* __restrict__ ln2_w, const float* __restrict__ ln2_b,
    const float* __restrict__ att_tmk, const float* __restrict__ att_tmv,
    const float* __restrict__ att_tmr, const float* __restrict__ att_tf,
    const float* __restrict__ att_td, const float* __restrict__ att_kw,
    const float* __restrict__ att_vw, const float* __restrict__ att_rw,
    const float* __restrict__ att_ow, const float* __restrict__ ffn_tmk,
    const float* __restrict__ ffn_tmr, const float* __restrict__ ffn_kw,
    const float* __restrict__ ffn_vw, const float* __restrict__ ffn_rw,
    const float* __restrict__ out_ln_w, const float* __restrict__ out_ln_b,
    const float* __restrict__ head_w,
    float* __restrict__ out_logits, float* __restrict__ out_state) {

    __shared__ float sh_a[DD];
    __shared__ float sh_b[DD];
    __shared__ float sh_c[DD];
    __shared__ float sh_k2[FF];
    __shared__ float red[64];

    const int tid = threadIdx.x;
    const int lane = tid & 31;
    const int wid = tid >> 5;
    const int gwarp = blockIdx.x * 32 + wid;
    unsigned sense = 0;

    // ===== encoder: x0 = LN(token_embd) =====
    {
        float v = token_embd[tid];
        float xn = block_ln(v, emb_ln_w[tid], emb_ln_b[tid], red);
        if (blockIdx.x == 0) g_x[tid] = xn;
        // prefetch layer 0 att weights (kw/vw/rw = 98304 lines of 128B)
        const char* b0 = (const char*)att_kw;
        const char* b1 = (const char*)att_vw;
        const char* b2 = (const char*)att_rw;
        for (unsigned off = (unsigned)gwarp * 32u + lane; off < 98304u; off += NTHREADS_TOTAL) {
            const char* p = off < 32768u ? b0 + (size_t)off * 128
                          : off < 65536u ? b1 + (size_t)(off - 32768u) * 128
                                         : b2 + (size_t)(off - 65536u) * 128;
            l2_prefetch(p);
        }
    }
    grid_sync(sense);  // barrier 1

    for (int l = 0; l < LL; ++l) {
        const size_t lD = (size_t)l * DD;
        const size_t lDD = (size_t)l * DD * DD;

        // ===== phase A: LN1 + time-mix interpolation + {kw,vw,rw} matvecs =====
        {
            float xcur = g_x[tid];
            float xn = block_ln(xcur, ln1_w[lD + tid], ln1_b[lD + tid], red);
            float s_att = state[(size_t)(l * 5 + 1) * DD + tid];
            float tmk = att_tmk[lD + tid], tmv = att_tmv[lD + tid], tmr = att_tmr[lD + tid];
            sh_a[tid] = xn * tmk + s_att * (1.f - tmk);
            sh_b[tid] = xn * tmv + s_att * (1.f - tmv);
            sh_c[tid] = xn * tmr + s_att * (1.f - tmr);
            if (blockIdx.x == 0) out_state[(size_t)(l * 5 + 1) * DD + tid] = xn;
            __syncthreads();

            if (gwarp < 3 * DD) {
                int m = gwarp >> 10;
                int rr = gwarp & (DD - 1);
                const float* W;
                const float* vin;
                if (m == 0)      { W = att_kw + lDD + (size_t)rr * DD; vin = sh_a; }
                else if (m == 1) { W = att_vw + lDD + (size_t)rr * DD; vin = sh_b; }
                else             { W = att_rw + lDD + (size_t)rr * DD; vin = sh_c; }
                float acc = dot1024(W, vin, lane);
                if (lane == 0) {
                    if (m == 0)      g_kk[rr] = acc;
                    else if (m == 1) g_vv[rr] = acc;
                    else             g_r[rr] = 1.f / (1.f + __expf(-acc));
                }
            } else {
                // idle warps (1664): prefetch ow + frw + first half of fkw (131072 lines)
                unsigned pw = (unsigned)(gwarp - 3 * DD);
                const char* owb  = (const char*)(att_ow + lDD);
                const char* frwb = (const char*)(ffn_rw + lDD);
                const char* fkwb = (const char*)(ffn_kw + (size_t)l * FF * DD);
                for (unsigned off = pw * 32u + lane; off < 131072u; off += 53248u) {
                    const char* p = off < 32768u ? owb + (size_t)off * 128
                                  : off < 65536u ? frwb + (size_t)(off - 32768u) * 128
                                                 : fkwb + (size_t)(off - 65536u) * 128;
                    l2_prefetch(p);
                }
            }
        }
        grid_sync(sense);

        // ===== phase B: WKV elementwise + ow matvec into x =====
        {
            float kk = g_kk[tid], vv = g_vv[tid], r = g_r[tid];
            float aa = state[(size_t)(l * 5 + 2) * DD + tid];
            float bb = state[(size_t)(l * 5 + 3) * DD + tid];
            float pp = state[(size_t)(l * 5 + 4) * DD + tid];
            float tf = att_tf[lD + tid];
            float td = att_td[lD + tid];
            float ww = tf + kk;
            float p = fmaxf(pp, ww);
            float e1 = expf(pp - p);
            float e2 = expf(ww - p);
            float a = e1 * aa + e2 * vv;
            float b = e1 * bb + e2;
            sh_a[tid] = r * (a / b);  // rab
            float ww2 = pp + td;
            float p2 = fmaxf(ww2, kk);
            float f1 = expf(ww2 - p2);
            float f2 = expf(kk - p2);
            if (blockIdx.x == 0) {
                out_state[(size_t)(l * 5 + 2) * DD + tid] = f1 * aa + f2 * vv;
                out_state[(size_t)(l * 5 + 3) * DD + tid] = f1 * bb + f2;
                out_state[(size_t)(l * 5 + 4) * DD + tid] = p2;
            }
            __syncthreads();

            // ow @ rab : 1024 rows, 4 warps/row, 8 rows/block/iter
            for (int g = blockIdx.x; g < 128; g += NB) {
                int rloc = wid >> 2;
                int chunk = wid & 3;
                int row = g * 8 + rloc;
                const float4* w4 = (const float4*)(att_ow + lDD + (size_t)row * DD) + chunk * 64;
                const float4* v4 = (const float4*)sh_a + chunk * 64;
                float acc = 0.f;
#pragma unroll
                for (int i = lane; i < 64; i += 32) {
                    float4 aw = __ldcs(&w4[i]);
                    float4 bv = v4[i];
                    acc += aw.x * bv.x + aw.y * bv.y + aw.z * bv.z + aw.w * bv.w;
                }
#pragma unroll
                for (int o = 16; o > 0; o >>= 1) acc += __shfl_xor_sync(0xffffffffu, acc, o);
                if (lane == 0) red[wid] = acc;
                __syncthreads();
                if (tid < 8) {
                    int row2 = g * 8 + tid;
                    float sum = red[tid * 4] + red[tid * 4 + 1] + red[tid * 4 + 2] + red[tid * 4 + 3];
                    g_x[row2] += sum;
                }
                __syncthreads();
            }

            // prefetch fkw 2nd half + fvw 1st half (131072 lines)
            const char* fkwb = (const char*)(ffn_kw + (size_t)l * FF * DD) + (size_t)65536 * 128;
            const char* fvwb = (const char*)(ffn_vw + (size_t)l * DD * FF);
            for (unsigned off = (unsigned)gwarp * 32u + lane; off < 131072u; off += NTHREADS_TOTAL) {
                const char* p = off < 65536u ? fkwb + (size_t)off * 128
                                             : fvwb + (size_t)(off - 65536u) * 128;
                l2_prefetch(p);
            }
        }
        grid_sync(sense);

        // ===== phase C: LN2 + channel-mix interpolation + {fkw,frw} matvecs =====
        {
            float xcur = g_x[tid];
            float xn2 = block_ln(xcur, ln2_w[lD + tid], ln2_b[lD + tid], red);
            float s_ffn = state[(size_t)(l * 5 + 0) * DD + tid];
            float tmk = ffn_tmk[lD + tid], tmr = ffn_tmr[lD + tid];
            sh_a[tid] = xn2 * tmk + s_ffn * (1.f - tmk);
            sh_b[tid] = xn2 * tmr + s_ffn * (1.f - tmr);
            if (blockIdx.x == 0) out_state[(size_t)(l * 5 + 0) * DD + tid] = xn2;
            __syncthreads();

            if (gwarp < FF) {
                // fkw rows 0..4095, one per warp
                const float* W = ffn_kw + (size_t)l * FF * DD + (size_t)gwarp * DD;
                float acc = dot1024(W, sh_a, lane);
                if (lane == 0) {
                    float t = fmaxf(acc, 0.f);
                    g_k2[gwarp] = t * t;
                }
            } else {
                // frw rows: 640 leftover warps cover 1024 rows (2-row batch where needed)
                int w = gwarp - FF;          // 0..639
                int r0 = w, r1 = w + 640;
                if (r1 < DD) {
                    float a0, a1;
                    dot1024x2(ffn_rw + lDD + (size_t)r0 * DD,
                              ffn_rw + lDD + (size_t)r1 * DD, sh_b, lane, a0, a1);
                    if (lane == 0) {
                        g_r2[r0] = 1.f / (1.f + __expf(-a0));
                        g_r2[r1] = 1.f / (1.f + __expf(-a1));
                    }
                } else {
                    float acc = dot1024(ffn_rw + lDD + (size_t)r0 * DD, sh_b, lane);
                    if (lane == 0) g_r2[r0] = 1.f / (1.f + __expf(-acc));
                }
            }

            // prefetch fvw 2nd half (65536 lines)
            const char* fvwb = (const char*)(ffn_vw + (size_t)l * DD * FF) + (size_t)65536 * 128;
            for (unsigned off = (unsigned)gwarp * 32u + lane; off < 65536u; off += NTHREADS_TOTAL)
                l2_prefetch(fvwb + (size_t)off * 128);
        }
        grid_sync(sense);

        // ===== phase D: x += r2 * (fvw @ k2), rescale =====
        {
            for (int i = tid; i < FF; i += NT) sh_k2[i] = g_k2[i];
            __syncthreads();
            float scale = ((l + 1) % 6 == 0) ? 0.5f : 1.0f;
            for (int g = blockIdx.x; g < 128; g += NB) {
                int rloc = wid >> 2;
                int chunk = wid & 3;
                int row = g * 8 + rloc;
                const float4* w4 =
                    (const float4*)(ffn_vw + (size_t)l * DD * FF + (size_t)row * FF) + chunk * 256;
                const float4* v4 = (const float4*)sh_k2 + chunk * 256;
                float acc = 0.f;
#pragma unroll
                for (int i = lane; i < 256; i += 32) {
                    float4 aw = __ldcs(&w4[i]);
                    float4 bv = v4[i];
                    acc += aw.x * bv.x + aw.y * bv.y + aw.z * bv.z + aw.w * bv.w;
                }
#pragma unroll
                for (int o = 16; o > 0; o >>= 1) acc += __shfl_xor_sync(0xffffffffu, acc, o);
                if (lane == 0) red[wid] = acc;
                __syncthreads();
                if (tid < 8) {
                    int row2 = g * 8 + tid;
                    float sum = red[tid * 4] + red[tid * 4 + 1] + red[tid * 4 + 2] + red[tid * 4 + 3];
                    g_x[row2] = (g_x[row2] + g_r2[row2] * sum) * scale;
                }
                __syncthreads();
            }

            // prefetch next layer's {kw,vw,rw} (98304 lines) — or head_w prefix at last layer
            if (l + 1 < LL) {
                const char* b0 = (const char*)(att_kw + (size_t)(l + 1) * DD * DD);
                const char* b1 = (const char*)(att_vw + (size_t)(l + 1) * DD * DD);
                const char* b2 = (const char*)(att_rw + (size_t)(l + 1) * DD * DD);
                for (unsigned off = (unsigned)gwarp * 32u + lane; off < 98304u; off += NTHREADS_TOTAL) {
                    const char* p = off < 32768u ? b0 + (size_t)off * 128
                                  : off < 65536u ? b1 + (size_t)(off - 32768u) * 128
                                                 : b2 + (size_t)(off - 65536u) * 128;
                    l2_prefetch(p);
                }
            } else {
                const char* hb = (const char*)head_w;
                for (unsigned off = (unsigned)gwarp * 32u + lane; off < 196608u; off += NTHREADS_TOTAL)
                    l2_prefetch(hb + (size_t)off * 128);
            }
        }
        grid_sync(sense);
    }

    // parity barrier (total grid_syncs must stay even: 1 + 24*4 + 1 = 98)
    grid_sync(sense);  // barrier 98

    // ===== head: logits = head_w @ LN(x), 2 rows per batch per warp =====
    {
        float v = g_x[tid];
        float xf = block_ln(v, out_ln_w[tid], out_ln_b[tid], red);
        sh_a[tid] = xf;
        __syncthreads();
        for (int row = gwarp; row < VV; row += 2 * NWARPS_TOTAL) {
            int row2 = row + NWARPS_TOTAL;
            if (row2 < VV) {
                float a0, a1;
                dot1024x2(head_w + (size_t)row * DD, head_w + (size_t)row2 * DD,
                          sh_a, lane, a0, a1);
                if (lane == 0) { out_logits[row] = a0; out_logits[row2] = a1; }
            } else {
                float acc = dot1024(head_w + (size_t)row * DD, sh_a, lane);
                if (lane == 0) out_logits[row] = acc;
            }
        }
    }
}

extern "C" void kernel_launch(void* const* d_in, const int* in_sizes, int n_in,
                              void* d_out, int out_size) {
    const float* token_embd = (const float*)d_in[0];
    const float* state      = (const float*)d_in[1];
    const float* emb_ln_w   = (const float*)d_in[2];
    const float* emb_ln_b   = (const float*)d_in[3];
    const float* ln1_w      = (const float*)d_in[4];
    const float* ln1_b      = (const float*)d_in[5];
    const float* ln2_w      = (const float*)d_in[6];
    const float* ln2_b      = (const float*)d_in[7];
    const float* att_tmk    = (const float*)d_in[8];
    const float* att_tmv    = (const float*)d_in[9];
    const float* att_tmr    = (const float*)d_in[10];
    const float* att_tf     = (const float*)d_in[11];
    const float* att_td     = (const float*)d_in[12];
    const float* att_kw     = (const float*)d_in[13];
    const float* att_vw     = (const float*)d_in[14];
    const float* att_rw     = (const float*)d_in[15];
    const float* att_ow     = (const float*)d_in[16];
    const float* ffn_tmk    = (const float*)d_in[17];
    const float* ffn_tmr    = (const float*)d_in[18];
    const float* ffn_kw     = (const float*)d_in[19];
    const float* ffn_vw     = (const float*)d_in[20];
    const float* ffn_rw     = (const float*)d_in[21];
    const float* out_ln_w   = (const float*)d_in[22];
    const float* out_ln_b   = (const float*)d_in[23];
    const float* head_w     = (const float*)d_in[24];

    float* out_logits = (float*)d_out;                 // V = 50277
    float* out_state  = (float*)d_out + VV;            // L*5*D = 122880

    rwkv_kernel<<<NB, NT>>>(token_embd, state, emb_ln_w, emb_ln_b, ln1_w, ln1_b,
                            ln2_w, ln2_b, att_tmk, att_tmv, att_tmr, att_tf,
                            att_td, att_kw, att_vw, att_rw, att_ow, ffn_tmk,
                            ffn_tmr, ffn_kw, ffn_vw, ffn_rw, out_ln_w, out_ln_b,
                            head_w, out_logits, out_state);
}